// round 2
// baseline (speedup 1.0000x reference)
#include <cuda_runtime.h>
#include <math.h>

#define N_STATIONS 100000
#define N_TIME     1000
#define K_NEIGH    8
#define SMOOTH_C   0.2f
#define KEEP_C     0.8f
#define N_COMP     4
#define COEFF_STRIDE 20   // 10 coeffs, each duplicated: {off,off,trend,trend,A0,A0,...}
#define TABLE_STRIDE 12   // t, s0..s3, c0..c3, pad, pad, pad
#define CHUNKS     250    // 1000 times / 4 per thread
#define SPB        64     // stations per block in main kernel

// Scratch (no cudaMalloc allowed)
__device__ float g_coeff[N_STATIONS * COEFF_STRIDE];
__device__ float g_table[N_TIME * TABLE_STRIDE];

// ---- packed f32x2 helpers ---------------------------------------------------
__device__ __forceinline__ unsigned long long pk2(float lo, float hi) {
    unsigned long long r;
    asm("mov.b64 %0, {%1, %2};" : "=l"(r) : "f"(lo), "f"(hi));
    return r;
}
__device__ __forceinline__ unsigned long long fma2(unsigned long long a,
                                                   unsigned long long b,
                                                   unsigned long long c) {
    unsigned long long d;
    asm("fma.rn.f32x2 %0, %1, %2, %3;" : "=l"(d) : "l"(a), "l"(b), "l"(c));
    return d;
}

// ---------------------------------------------------------------------------
// Kernel 1: neighbor smoothing -> duplicated per-station coefficients.
//   A_i = amp_s * cos(ph_s)  (x sin(wt)),  B_i = amp_s * sin(ph_s)  (x cos(wt))
//   cos(atan2(im,re)) = re * rsqrt(re^2+im^2)  -> no atan2 needed.
// First N_TIME global threads also build the time table (fused launch).
// ---------------------------------------------------------------------------
__global__ void smooth_kernel(const float* __restrict__ off,
                              const float* __restrict__ trend,
                              const float* __restrict__ amps,
                              const float* __restrict__ phases,
                              const int*   __restrict__ nidx,
                              const float* __restrict__ nw,
                              const float* __restrict__ time_vector,
                              const float* __restrict__ periods)
{
    int st = blockIdx.x * blockDim.x + threadIdx.x;

    // fused time-table build (accurate sincosf; args < ~130 rad)
    if (st < N_TIME) {
        float t = time_vector[st];
        float e[TABLE_STRIDE];
        e[0] = t;
#pragma unroll
        for (int i = 0; i < N_COMP; ++i) {
            float w = 6.2831853071795864769f / periods[i];
            float sv, cv;
            sincosf(w * t, &sv, &cv);
            e[1 + i] = sv;
            e[5 + i] = cv;
        }
        e[9] = 0.f; e[10] = 0.f; e[11] = 0.f;
        float4* dst = reinterpret_cast<float4*>(g_table + st * TABLE_STRIDE);
        dst[0] = make_float4(e[0], e[1], e[2],  e[3]);
        dst[1] = make_float4(e[4], e[5], e[6],  e[7]);
        dst[2] = make_float4(e[8], e[9], e[10], e[11]);
    }

    if (st >= N_STATIONS) return;

    float avg_amp[N_COMP] = {0.f, 0.f, 0.f, 0.f};
    float avg_re [N_COMP] = {0.f, 0.f, 0.f, 0.f};
    float avg_im [N_COMP] = {0.f, 0.f, 0.f, 0.f};

    // front-load indices/weights for MLP
    int4   ni0 = reinterpret_cast<const int4*>(nidx + st * K_NEIGH)[0];
    int4   ni1 = reinterpret_cast<const int4*>(nidx + st * K_NEIGH)[1];
    float4 w0  = reinterpret_cast<const float4*>(nw + st * K_NEIGH)[0];
    float4 w1  = reinterpret_cast<const float4*>(nw + st * K_NEIGH)[1];
    int   nbv[K_NEIGH] = {ni0.x, ni0.y, ni0.z, ni0.w, ni1.x, ni1.y, ni1.z, ni1.w};
    float wv [K_NEIGH] = {w0.x,  w0.y,  w0.z,  w0.w,  w1.x,  w1.y,  w1.z,  w1.w};

#pragma unroll
    for (int k = 0; k < K_NEIGH; ++k) {
        int   nb = nbv[k];
        float w  = wv[k];
        const float4 na = *reinterpret_cast<const float4*>(amps   + nb * 4);
        const float4 np = *reinterpret_cast<const float4*>(phases + nb * 4);
        float av[4] = {na.x, na.y, na.z, na.w};
        float pv[4] = {np.x, np.y, np.z, np.w};
#pragma unroll
        for (int i = 0; i < N_COMP; ++i) {
            avg_amp[i] = fmaf(w, av[i], avg_amp[i]);
            float sp, cp;
            __sincosf(pv[i], &sp, &cp);
            avg_re[i] = fmaf(w, cp, avg_re[i]);
            avg_im[i] = fmaf(w, sp, avg_im[i]);
        }
    }

    const float4 oa = *reinterpret_cast<const float4*>(amps   + st * 4);
    const float4 op = *reinterpret_cast<const float4*>(phases + st * 4);
    float a0[4] = {oa.x, oa.y, oa.z, oa.w};
    float p0[4] = {op.x, op.y, op.z, op.w};

    float A[N_COMP], B[N_COMP];
#pragma unroll
    for (int i = 0; i < N_COMP; ++i) {
        float amp_s = KEEP_C * a0[i] + SMOOTH_C * avg_amp[i];
        float sp, cp;
        __sincosf(p0[i], &sp, &cp);
        float mr = KEEP_C * cp + SMOOTH_C * avg_re[i];
        float mi = KEEP_C * sp + SMOOTH_C * avg_im[i];
        float inv = rsqrtf(fmaxf(mr * mr + mi * mi, 1e-30f));
        A[i] = amp_s * mr * inv;
        B[i] = amp_s * mi * inv;
    }

    float o = off[st];
    float tr = trend[st];
    float4* dst = reinterpret_cast<float4*>(g_coeff + st * COEFF_STRIDE);
    dst[0] = make_float4(o,    o,    tr,   tr);
    dst[1] = make_float4(A[0], A[0], A[1], A[1]);
    dst[2] = make_float4(A[2], A[2], A[3], A[3]);
    dst[3] = make_float4(B[0], B[0], B[1], B[1]);
    dst[4] = make_float4(B[2], B[2], B[3], B[3]);
}

// ---------------------------------------------------------------------------
// Kernel 2: main evaluation with packed f32x2 FMAs.
// Thread owns 4 times (2 packed pairs); table lives in registers; coefficients
// arrive pre-duplicated so each LDG.128 yields two ready {k,k} f32x2 operands.
// 18 FFMA2 per station-thread (was 36 FFMA). STG.128 coalesced stores.
// ---------------------------------------------------------------------------
__global__ void __launch_bounds__(256) eval_kernel(float* __restrict__ out)
{
    const int  col    = threadIdx.x;       // 0..255 ; chunks 0..249 real
    const bool active = (col < CHUNKS);

    unsigned long long tt2[2];
    unsigned long long ss2[2][4];
    unsigned long long cc2[2][4];

    if (active) {
#pragma unroll
        for (int h = 0; h < 2; ++h) {
            const float* tpA = g_table + (col * 4 + 2 * h)     * TABLE_STRIDE;
            const float* tpB = g_table + (col * 4 + 2 * h + 1) * TABLE_STRIDE;
            float4 a0 = reinterpret_cast<const float4*>(tpA)[0];
            float4 a1 = reinterpret_cast<const float4*>(tpA)[1];
            float4 a2 = reinterpret_cast<const float4*>(tpA)[2];
            float4 b0 = reinterpret_cast<const float4*>(tpB)[0];
            float4 b1 = reinterpret_cast<const float4*>(tpB)[1];
            float4 b2 = reinterpret_cast<const float4*>(tpB)[2];
            tt2[h]    = pk2(a0.x, b0.x);
            ss2[h][0] = pk2(a0.y, b0.y);
            ss2[h][1] = pk2(a0.z, b0.z);
            ss2[h][2] = pk2(a0.w, b0.w);
            ss2[h][3] = pk2(a1.x, b1.x);
            cc2[h][0] = pk2(a1.y, b1.y);
            cc2[h][1] = pk2(a1.z, b1.z);
            cc2[h][2] = pk2(a1.w, b1.w);
            cc2[h][3] = pk2(a2.x, b2.x);
        }
    }

    int s0 = blockIdx.x * SPB;
    int s1 = min(s0 + SPB, N_STATIONS);

    for (int st = s0; st < s1; ++st) {
        const ulonglong2* cp =
            reinterpret_cast<const ulonglong2*>(g_coeff + st * COEFF_STRIDE);
        ulonglong2 x0 = cp[0];  // {off,off},{trend,trend}
        ulonglong2 x1 = cp[1];  // {A0,A0},{A1,A1}
        ulonglong2 x2 = cp[2];  // {A2,A2},{A3,A3}
        ulonglong2 x3 = cp[3];  // {B0,B0},{B1,B1}
        ulonglong2 x4 = cp[4];  // {B2,B2},{B3,B3}
        if (active) {
            unsigned long long r[2];
#pragma unroll
            for (int h = 0; h < 2; ++h) {
                unsigned long long v = fma2(x0.y, tt2[h], x0.x);
                v = fma2(x1.x, ss2[h][0], v);
                v = fma2(x1.y, ss2[h][1], v);
                v = fma2(x2.x, ss2[h][2], v);
                v = fma2(x2.y, ss2[h][3], v);
                v = fma2(x3.x, cc2[h][0], v);
                v = fma2(x3.y, cc2[h][1], v);
                v = fma2(x4.x, cc2[h][2], v);
                v = fma2(x4.y, cc2[h][3], v);
                r[h] = v;
            }
            ulonglong2* optr = reinterpret_cast<ulonglong2*>(
                out + (size_t)st * N_TIME + col * 4);
            *optr = make_ulonglong2(r[0], r[1]);
        }
    }
}

// ---------------------------------------------------------------------------
extern "C" void kernel_launch(void* const* d_in, const int* in_sizes, int n_in,
                              void* d_out, int out_size)
{
    const float* time_vector = (const float*)d_in[0];
    const float* off         = (const float*)d_in[1];
    const float* trend       = (const float*)d_in[2];
    const float* amps        = (const float*)d_in[3];
    const float* phases      = (const float*)d_in[4];
    const int*   nidx        = (const int*)  d_in[5];
    const float* nw          = (const float*)d_in[6];
    const float* periods     = (const float*)d_in[7];
    float* out = (float*)d_out;

    smooth_kernel<<<(N_STATIONS + 255) / 256, 256>>>(
        off, trend, amps, phases, nidx, nw, time_vector, periods);
    eval_kernel<<<(N_STATIONS + SPB - 1) / SPB, 256>>>(out);
}

// round 3
// speedup vs baseline: 1.3778x; 1.3778x over previous
#include <cuda_runtime.h>
#include <math.h>

#define N_STATIONS 100000
#define N_TIME     1000
#define K_NEIGH    8
#define SMOOTH_C   0.2f
#define KEEP_C     0.8f
#define N_COMP     4
#define COEFF_STRIDE 20   // 10 coeffs, each duplicated as {k,k} pairs
#define TABLE_STRIDE 12   // t, s0..s3, c0..c3, pad x3
#define CHUNKS     250    // 1000 times / 4 per thread
#define SPB        64     // stations per block in eval

// Scratch (no cudaMalloc allowed)
__device__ float g_coeff[N_STATIONS * COEFF_STRIDE];
__device__ float g_table[N_TIME * TABLE_STRIDE];

typedef unsigned long long u64;

// ---- packed f32x2 helpers ---------------------------------------------------
__device__ __forceinline__ u64 pk2(float lo, float hi) {
    u64 r; asm("mov.b64 %0, {%1, %2};" : "=l"(r) : "f"(lo), "f"(hi)); return r;
}
__device__ __forceinline__ u64 fma2(u64 a, u64 b, u64 c) {
    u64 d; asm("fma.rn.f32x2 %0, %1, %2, %3;" : "=l"(d) : "l"(a), "l"(b), "l"(c)); return d;
}
__device__ __forceinline__ u64 mul2(u64 a, u64 b) {
    u64 d; asm("mul.rn.f32x2 %0, %1, %2;" : "=l"(d) : "l"(a), "l"(b)); return d;
}
__device__ __forceinline__ u64 add2(u64 a, u64 b) {
    u64 d; asm("add.rn.f32x2 %0, %1, %2;" : "=l"(d) : "l"(a), "l"(b)); return d;
}
__device__ __forceinline__ void stcs2(void* p, u64 a, u64 b) {
    asm volatile("st.global.cs.v2.u64 [%0], {%1, %2};" :: "l"(p), "l"(a), "l"(b) : "memory");
}

// ---------------------------------------------------------------------------
// Kernel 1: neighbor smoothing -> duplicated per-station coefficients.
//   A_i = amp_s*cos(ph_s) (x sin(wt)),  B_i = amp_s*sin(ph_s) (x cos(wt))
//   cos(atan2(im,re)) = re*rsqrt(re^2+im^2) -> no atan2.
// First N_TIME global threads also build the time table (fused).
// ---------------------------------------------------------------------------
__global__ void smooth_kernel(const float* __restrict__ off,
                              const float* __restrict__ trend,
                              const float* __restrict__ amps,
                              const float* __restrict__ phases,
                              const int*   __restrict__ nidx,
                              const float* __restrict__ nw,
                              const float* __restrict__ time_vector,
                              const float* __restrict__ periods)
{
    int st = blockIdx.x * blockDim.x + threadIdx.x;

    if (st < N_TIME) {
        float t = time_vector[st];
        float e[TABLE_STRIDE];
        e[0] = t;
#pragma unroll
        for (int i = 0; i < N_COMP; ++i) {
            float w = 6.2831853071795864769f / periods[i];
            float sv, cv;
            sincosf(w * t, &sv, &cv);   // precise; args < ~130 rad
            e[1 + i] = sv;
            e[5 + i] = cv;
        }
        e[9] = 0.f; e[10] = 0.f; e[11] = 0.f;
        float4* dst = reinterpret_cast<float4*>(g_table + st * TABLE_STRIDE);
        dst[0] = make_float4(e[0], e[1], e[2],  e[3]);
        dst[1] = make_float4(e[4], e[5], e[6],  e[7]);
        dst[2] = make_float4(e[8], e[9], e[10], e[11]);
    }

    if (st >= N_STATIONS) return;

    float avg_amp[N_COMP] = {0.f, 0.f, 0.f, 0.f};
    float avg_re [N_COMP] = {0.f, 0.f, 0.f, 0.f};
    float avg_im [N_COMP] = {0.f, 0.f, 0.f, 0.f};

    int4   ni0 = reinterpret_cast<const int4*>(nidx + st * K_NEIGH)[0];
    int4   ni1 = reinterpret_cast<const int4*>(nidx + st * K_NEIGH)[1];
    float4 w0  = reinterpret_cast<const float4*>(nw + st * K_NEIGH)[0];
    float4 w1  = reinterpret_cast<const float4*>(nw + st * K_NEIGH)[1];
    int   nbv[K_NEIGH] = {ni0.x, ni0.y, ni0.z, ni0.w, ni1.x, ni1.y, ni1.z, ni1.w};
    float wv [K_NEIGH] = {w0.x,  w0.y,  w0.z,  w0.w,  w1.x,  w1.y,  w1.z,  w1.w};

#pragma unroll
    for (int k = 0; k < K_NEIGH; ++k) {
        int   nb = nbv[k];
        float w  = wv[k];
        const float4 na = *reinterpret_cast<const float4*>(amps   + nb * 4);
        const float4 np = *reinterpret_cast<const float4*>(phases + nb * 4);
        float av[4] = {na.x, na.y, na.z, na.w};
        float pv[4] = {np.x, np.y, np.z, np.w};
#pragma unroll
        for (int i = 0; i < N_COMP; ++i) {
            avg_amp[i] = fmaf(w, av[i], avg_amp[i]);
            float sp, cp;
            __sincosf(pv[i], &sp, &cp);
            avg_re[i] = fmaf(w, cp, avg_re[i]);
            avg_im[i] = fmaf(w, sp, avg_im[i]);
        }
    }

    const float4 oa = *reinterpret_cast<const float4*>(amps   + st * 4);
    const float4 op = *reinterpret_cast<const float4*>(phases + st * 4);
    float a0[4] = {oa.x, oa.y, oa.z, oa.w};
    float p0[4] = {op.x, op.y, op.z, op.w};

    float A[N_COMP], B[N_COMP];
#pragma unroll
    for (int i = 0; i < N_COMP; ++i) {
        float amp_s = KEEP_C * a0[i] + SMOOTH_C * avg_amp[i];
        float sp, cp;
        __sincosf(p0[i], &sp, &cp);
        float mr = KEEP_C * cp + SMOOTH_C * avg_re[i];
        float mi = KEEP_C * sp + SMOOTH_C * avg_im[i];
        float inv = rsqrtf(fmaxf(mr * mr + mi * mi, 1e-30f));
        A[i] = amp_s * mr * inv;
        B[i] = amp_s * mi * inv;
    }

    float o = off[st];
    float tr = trend[st];
    float4* dst = reinterpret_cast<float4*>(g_coeff + st * COEFF_STRIDE);
    dst[0] = make_float4(o,    o,    tr,   tr);
    dst[1] = make_float4(A[0], A[0], A[1], A[1]);
    dst[2] = make_float4(A[2], A[2], A[3], A[3]);
    dst[3] = make_float4(B[0], B[0], B[1], B[1]);
    dst[4] = make_float4(B[2], B[2], B[3], B[3]);
}

// ---------------------------------------------------------------------------
// Kernel 2: evaluation. Thread owns 4 times (2 f32x2 pairs, table in regs).
// Station loop unrolled x2: 10 front-batched LDG.128 (MLP=10), then two
// stations' worth of tree-structured FMA2 (3 independent partials, depth ~5),
// streaming v2.u64 stores.
// ---------------------------------------------------------------------------
__global__ void __launch_bounds__(256) eval_kernel(float* __restrict__ out)
{
    const int  col    = threadIdx.x;       // chunks 0..249 real
    const bool active = (col < CHUNKS);

    u64 tt2[2];
    u64 ss2[2][4];
    u64 cc2[2][4];

    if (active) {
#pragma unroll
        for (int h = 0; h < 2; ++h) {
            const float* tpA = g_table + (col * 4 + 2 * h)     * TABLE_STRIDE;
            const float* tpB = g_table + (col * 4 + 2 * h + 1) * TABLE_STRIDE;
            float4 a0 = reinterpret_cast<const float4*>(tpA)[0];
            float4 a1 = reinterpret_cast<const float4*>(tpA)[1];
            float4 a2 = reinterpret_cast<const float4*>(tpA)[2];
            float4 b0 = reinterpret_cast<const float4*>(tpB)[0];
            float4 b1 = reinterpret_cast<const float4*>(tpB)[1];
            float4 b2 = reinterpret_cast<const float4*>(tpB)[2];
            tt2[h]    = pk2(a0.x, b0.x);
            ss2[h][0] = pk2(a0.y, b0.y);
            ss2[h][1] = pk2(a0.z, b0.z);
            ss2[h][2] = pk2(a0.w, b0.w);
            ss2[h][3] = pk2(a1.x, b1.x);
            cc2[h][0] = pk2(a1.y, b1.y);
            cc2[h][1] = pk2(a1.z, b1.z);
            cc2[h][2] = pk2(a1.w, b1.w);
            cc2[h][3] = pk2(a2.x, b2.x);
        }
    }

    const int s0 = blockIdx.x * SPB;
    const int s1 = min(s0 + SPB, N_STATIONS);   // always even count

    for (int st = s0; st < s1; st += 2) {
        // front-batch ALL loads for two stations (MLP = 10)
        const ulonglong2* cpa =
            reinterpret_cast<const ulonglong2*>(g_coeff + st * COEFF_STRIDE);
        const ulonglong2* cpb =
            reinterpret_cast<const ulonglong2*>(g_coeff + (st + 1) * COEFF_STRIDE);
        ulonglong2 xa0 = __ldg(cpa + 0), xa1 = __ldg(cpa + 1), xa2 = __ldg(cpa + 2),
                   xa3 = __ldg(cpa + 3), xa4 = __ldg(cpa + 4);
        ulonglong2 xb0 = __ldg(cpb + 0), xb1 = __ldg(cpb + 1), xb2 = __ldg(cpb + 2),
                   xb3 = __ldg(cpb + 3), xb4 = __ldg(cpb + 4);

        if (active) {
            u64 ra[2], rb[2];
#pragma unroll
            for (int h = 0; h < 2; ++h) {
                // station st: three independent partial chains (depth ~5)
                u64 p0 = fma2(xa0.y, tt2[h],    xa0.x);   // off + trend*t
                u64 p1 = mul2(xa1.x, ss2[h][0]);          // A0*s0
                u64 p2 = mul2(xa1.y, ss2[h][1]);          // A1*s1
                p0 = fma2(xa2.x, ss2[h][2], p0);          // +A2*s2
                p1 = fma2(xa2.y, ss2[h][3], p1);          // +A3*s3
                p2 = fma2(xa3.x, cc2[h][0], p2);          // +B0*c0
                p0 = fma2(xa3.y, cc2[h][1], p0);          // +B1*c1
                p1 = fma2(xa4.x, cc2[h][2], p1);          // +B2*c2
                p2 = fma2(xa4.y, cc2[h][3], p2);          // +B3*c3
                ra[h] = add2(p0, add2(p1, p2));

                // station st+1
                u64 q0 = fma2(xb0.y, tt2[h],    xb0.x);
                u64 q1 = mul2(xb1.x, ss2[h][0]);
                u64 q2 = mul2(xb1.y, ss2[h][1]);
                q0 = fma2(xb2.x, ss2[h][2], q0);
                q1 = fma2(xb2.y, ss2[h][3], q1);
                q2 = fma2(xb3.x, cc2[h][0], q2);
                q0 = fma2(xb3.y, cc2[h][1], q0);
                q1 = fma2(xb4.x, cc2[h][2], q1);
                q2 = fma2(xb4.y, cc2[h][3], q2);
                rb[h] = add2(q0, add2(q1, q2));
            }
            stcs2(out + (size_t)st * N_TIME + col * 4,       ra[0], ra[1]);
            stcs2(out + (size_t)(st + 1) * N_TIME + col * 4, rb[0], rb[1]);
        }
    }
}

// ---------------------------------------------------------------------------
extern "C" void kernel_launch(void* const* d_in, const int* in_sizes, int n_in,
                              void* d_out, int out_size)
{
    const float* time_vector = (const float*)d_in[0];
    const float* off         = (const float*)d_in[1];
    const float* trend       = (const float*)d_in[2];
    const float* amps        = (const float*)d_in[3];
    const float* phases      = (const float*)d_in[4];
    const int*   nidx        = (const int*)  d_in[5];
    const float* nw          = (const float*)d_in[6];
    const float* periods     = (const float*)d_in[7];
    float* out = (float*)d_out;

    smooth_kernel<<<(N_STATIONS + 255) / 256, 256>>>(
        off, trend, amps, phases, nidx, nw, time_vector, periods);
    eval_kernel<<<(N_STATIONS + SPB - 1) / SPB, 256>>>(out);
}

// round 4
// speedup vs baseline: 2.1397x; 1.5530x over previous
#include <cuda_runtime.h>
#include <math.h>

#define N_STATIONS 100000
#define N_TIME     1000
#define K_NEIGH    8
#define SMOOTH_C   0.2f
#define KEEP_C     0.8f
#define N_COMP     4
#define COEFF_STRIDE 20   // 10 coeffs, duplicated as {k,k} pairs = 5 float4
#define TABLE_STRIDE 12   // t, s0..s3, c0..c3, pad x3
#define CHUNKS     250    // 1000 times / 4 per thread
#define SPB        128    // stations per block in eval

// Scratch (no cudaMalloc allowed)
__device__ float g_coeff[N_STATIONS * COEFF_STRIDE];
__device__ float g_table[N_TIME * TABLE_STRIDE];

typedef unsigned long long u64;

// ---- packed f32x2 helpers ---------------------------------------------------
__device__ __forceinline__ u64 pk2(float lo, float hi) {
    u64 r; asm("mov.b64 %0, {%1, %2};" : "=l"(r) : "f"(lo), "f"(hi)); return r;
}
__device__ __forceinline__ u64 fma2(u64 a, u64 b, u64 c) {
    u64 d; asm("fma.rn.f32x2 %0, %1, %2, %3;" : "=l"(d) : "l"(a), "l"(b), "l"(c)); return d;
}
__device__ __forceinline__ u64 mul2(u64 a, u64 b) {
    u64 d; asm("mul.rn.f32x2 %0, %1, %2;" : "=l"(d) : "l"(a), "l"(b)); return d;
}
__device__ __forceinline__ u64 add2(u64 a, u64 b) {
    u64 d; asm("add.rn.f32x2 %0, %1, %2;" : "=l"(d) : "l"(a), "l"(b)); return d;
}
__device__ __forceinline__ void stcs2(void* p, u64 a, u64 b) {
    asm volatile("st.global.cs.v2.u64 [%0], {%1, %2};" :: "l"(p), "l"(a), "l"(b) : "memory");
}

// ---------------------------------------------------------------------------
// Kernel 1: neighbor smoothing -> duplicated per-station coefficients.
//   A_i = amp_s*cos(ph_s) (x sin(wt)),  B_i = amp_s*sin(ph_s) (x cos(wt))
//   cos(atan2(im,re)) = re*rsqrt(re^2+im^2) -> no atan2.
// First N_TIME global threads also build the time table (fused).
// ---------------------------------------------------------------------------
__global__ void smooth_kernel(const float* __restrict__ off,
                              const float* __restrict__ trend,
                              const float* __restrict__ amps,
                              const float* __restrict__ phases,
                              const int*   __restrict__ nidx,
                              const float* __restrict__ nw,
                              const float* __restrict__ time_vector,
                              const float* __restrict__ periods)
{
    int st = blockIdx.x * blockDim.x + threadIdx.x;

    if (st < N_TIME) {
        float t = time_vector[st];
        float e[TABLE_STRIDE];
        e[0] = t;
#pragma unroll
        for (int i = 0; i < N_COMP; ++i) {
            float w = 6.2831853071795864769f / periods[i];
            float sv, cv;
            sincosf(w * t, &sv, &cv);   // precise; args < ~130 rad
            e[1 + i] = sv;
            e[5 + i] = cv;
        }
        e[9] = 0.f; e[10] = 0.f; e[11] = 0.f;
        float4* dst = reinterpret_cast<float4*>(g_table + st * TABLE_STRIDE);
        dst[0] = make_float4(e[0], e[1], e[2],  e[3]);
        dst[1] = make_float4(e[4], e[5], e[6],  e[7]);
        dst[2] = make_float4(e[8], e[9], e[10], e[11]);
    }

    if (st >= N_STATIONS) return;

    float avg_amp[N_COMP] = {0.f, 0.f, 0.f, 0.f};
    float avg_re [N_COMP] = {0.f, 0.f, 0.f, 0.f};
    float avg_im [N_COMP] = {0.f, 0.f, 0.f, 0.f};

    int4   ni0 = reinterpret_cast<const int4*>(nidx + st * K_NEIGH)[0];
    int4   ni1 = reinterpret_cast<const int4*>(nidx + st * K_NEIGH)[1];
    float4 w0  = reinterpret_cast<const float4*>(nw + st * K_NEIGH)[0];
    float4 w1  = reinterpret_cast<const float4*>(nw + st * K_NEIGH)[1];
    int   nbv[K_NEIGH] = {ni0.x, ni0.y, ni0.z, ni0.w, ni1.x, ni1.y, ni1.z, ni1.w};
    float wv [K_NEIGH] = {w0.x,  w0.y,  w0.z,  w0.w,  w1.x,  w1.y,  w1.z,  w1.w};

#pragma unroll
    for (int k = 0; k < K_NEIGH; ++k) {
        int   nb = nbv[k];
        float w  = wv[k];
        const float4 na = *reinterpret_cast<const float4*>(amps   + nb * 4);
        const float4 np = *reinterpret_cast<const float4*>(phases + nb * 4);
        float av[4] = {na.x, na.y, na.z, na.w};
        float pv[4] = {np.x, np.y, np.z, np.w};
#pragma unroll
        for (int i = 0; i < N_COMP; ++i) {
            avg_amp[i] = fmaf(w, av[i], avg_amp[i]);
            float sp, cp;
            __sincosf(pv[i], &sp, &cp);
            avg_re[i] = fmaf(w, cp, avg_re[i]);
            avg_im[i] = fmaf(w, sp, avg_im[i]);
        }
    }

    const float4 oa = *reinterpret_cast<const float4*>(amps   + st * 4);
    const float4 op = *reinterpret_cast<const float4*>(phases + st * 4);
    float a0[4] = {oa.x, oa.y, oa.z, oa.w};
    float p0[4] = {op.x, op.y, op.z, op.w};

    float A[N_COMP], B[N_COMP];
#pragma unroll
    for (int i = 0; i < N_COMP; ++i) {
        float amp_s = KEEP_C * a0[i] + SMOOTH_C * avg_amp[i];
        float sp, cp;
        __sincosf(p0[i], &sp, &cp);
        float mr = KEEP_C * cp + SMOOTH_C * avg_re[i];
        float mi = KEEP_C * sp + SMOOTH_C * avg_im[i];
        float inv = rsqrtf(fmaxf(mr * mr + mi * mi, 1e-30f));
        A[i] = amp_s * mr * inv;
        B[i] = amp_s * mi * inv;
    }

    float o = off[st];
    float tr = trend[st];
    float4* dst = reinterpret_cast<float4*>(g_coeff + st * COEFF_STRIDE);
    dst[0] = make_float4(o,    o,    tr,   tr);
    dst[1] = make_float4(A[0], A[0], A[1], A[1]);
    dst[2] = make_float4(A[2], A[2], A[3], A[3]);
    dst[3] = make_float4(B[0], B[0], B[1], B[1]);
    dst[4] = make_float4(B[2], B[2], B[3], B[3]);
}

// ---------------------------------------------------------------------------
// Kernel 2: evaluation. Thread owns 4 times (2 f32x2 pairs; table in regs).
// Block stages SPB stations' coefficients in SHARED memory once (cooperative
// coalesced load + single __syncthreads). Inner loop reads coefficients via
// broadcast LDS.128 (29-cyc fixed latency, 1 wavefront) — zero inner-loop
// LDGs. Tree-structured FMA2 (3 independent chains), streaming STG.128.
// ---------------------------------------------------------------------------
__global__ void __launch_bounds__(256, 4) eval_kernel(float* __restrict__ out)
{
    __shared__ float4 s_coeff[SPB * 5];   // 10240 B

    const int  col    = threadIdx.x;      // chunks 0..249 real
    const bool active = (col < CHUNKS);

    const int s_base = blockIdx.x * SPB;
    const int ns     = min(SPB, N_STATIONS - s_base);

    // cooperative coalesced coefficient staging
    {
        const float4* gsrc = reinterpret_cast<const float4*>(g_coeff) + (size_t)s_base * 5;
        const int total_f4 = ns * 5;
        for (int i = threadIdx.x; i < total_f4; i += 256)
            s_coeff[i] = gsrc[i];
    }

    // per-thread time table in registers
    u64 tt2[2];
    u64 ss2[2][4];
    u64 cc2[2][4];
    if (active) {
#pragma unroll
        for (int h = 0; h < 2; ++h) {
            const float* tpA = g_table + (col * 4 + 2 * h)     * TABLE_STRIDE;
            const float* tpB = g_table + (col * 4 + 2 * h + 1) * TABLE_STRIDE;
            float4 a0 = reinterpret_cast<const float4*>(tpA)[0];
            float4 a1 = reinterpret_cast<const float4*>(tpA)[1];
            float4 a2 = reinterpret_cast<const float4*>(tpA)[2];
            float4 b0 = reinterpret_cast<const float4*>(tpB)[0];
            float4 b1 = reinterpret_cast<const float4*>(tpB)[1];
            float4 b2 = reinterpret_cast<const float4*>(tpB)[2];
            tt2[h]    = pk2(a0.x, b0.x);
            ss2[h][0] = pk2(a0.y, b0.y);
            ss2[h][1] = pk2(a0.z, b0.z);
            ss2[h][2] = pk2(a0.w, b0.w);
            ss2[h][3] = pk2(a1.x, b1.x);
            cc2[h][0] = pk2(a1.y, b1.y);
            cc2[h][1] = pk2(a1.z, b1.z);
            cc2[h][2] = pk2(a1.w, b1.w);
            cc2[h][3] = pk2(a2.x, b2.x);
        }
    }

    __syncthreads();

    for (int j = 0; j < ns; ++j) {
        // broadcast LDS.128 x5 — all lanes read the same address
        const ulonglong2* cp = reinterpret_cast<const ulonglong2*>(s_coeff + j * 5);
        ulonglong2 x0 = cp[0];  // {off,off},{trend,trend}
        ulonglong2 x1 = cp[1];  // {A0,A0},{A1,A1}
        ulonglong2 x2 = cp[2];  // {A2,A2},{A3,A3}
        ulonglong2 x3 = cp[3];  // {B0,B0},{B1,B1}
        ulonglong2 x4 = cp[4];  // {B2,B2},{B3,B3}

        if (active) {
            u64 r[2];
#pragma unroll
            for (int h = 0; h < 2; ++h) {
                u64 p0 = fma2(x0.y, tt2[h],    x0.x);   // off + trend*t
                u64 p1 = mul2(x1.x, ss2[h][0]);          // A0*s0
                u64 p2 = mul2(x1.y, ss2[h][1]);          // A1*s1
                p0 = fma2(x2.x, ss2[h][2], p0);          // +A2*s2
                p1 = fma2(x2.y, ss2[h][3], p1);          // +A3*s3
                p2 = fma2(x3.x, cc2[h][0], p2);          // +B0*c0
                p0 = fma2(x3.y, cc2[h][1], p0);          // +B1*c1
                p1 = fma2(x4.x, cc2[h][2], p1);          // +B2*c2
                p2 = fma2(x4.y, cc2[h][3], p2);          // +B3*c3
                r[h] = add2(p0, add2(p1, p2));
            }
            stcs2(out + (size_t)(s_base + j) * N_TIME + col * 4, r[0], r[1]);
        }
    }
}

// ---------------------------------------------------------------------------
extern "C" void kernel_launch(void* const* d_in, const int* in_sizes, int n_in,
                              void* d_out, int out_size)
{
    const float* time_vector = (const float*)d_in[0];
    const float* off         = (const float*)d_in[1];
    const float* trend       = (const float*)d_in[2];
    const float* amps        = (const float*)d_in[3];
    const float* phases      = (const float*)d_in[4];
    const int*   nidx        = (const int*)  d_in[5];
    const float* nw          = (const float*)d_in[6];
    const float* periods     = (const float*)d_in[7];
    float* out = (float*)d_out;

    smooth_kernel<<<(N_STATIONS + 255) / 256, 256>>>(
        off, trend, amps, phases, nidx, nw, time_vector, periods);
    eval_kernel<<<(N_STATIONS + SPB - 1) / SPB, 256>>>(out);
}